// round 6
// baseline (speedup 1.0000x reference)
#include <cuda_runtime.h>
#include <cuda_bf16.h>
#include <stdint.h>
#include <math.h>

#define BATCH 65536
#define DIN   64
#define HID   512

enum { EPI_TANH = 0, EPI_DA2 = 1, EPI_MULT = 2, EPI_SYMP = 3 };

// ---------------- scratch (__device__ globals; allocation-free rule) --------
__device__ int g_maxbits[8];  // [0]=x [1]=W0 [2]=W1 [3]=W2 [4]=W3 [5]=d1 [6]=d0
__device__ int8_t g_xh[(size_t)BATCH * DIN];
__device__ int8_t g_xl[(size_t)BATCH * DIN];
__device__ int8_t g_h0h[(size_t)BATCH * HID];
__device__ int8_t g_h0l[(size_t)BATCH * HID];
__device__ int8_t g_h1h[(size_t)BATCH * HID];
__device__ int8_t g_h1l[(size_t)BATCH * HID];
__device__ int8_t g_d2h[(size_t)BATCH * HID];
__device__ int8_t g_d2l[(size_t)BATCH * HID];
__device__ float  g_d1f[(size_t)BATCH * HID];
__device__ int8_t g_d1h[(size_t)BATCH * HID];
__device__ int8_t g_d1l[(size_t)BATCH * HID];
__device__ float  g_d0f[(size_t)BATCH * HID];
__device__ int8_t g_d0h[(size_t)BATCH * HID];
__device__ int8_t g_d0l[(size_t)BATCH * HID];
// weights, B-operand [N][K] row-major int8 pairs
__device__ int8_t g_bf0h[HID * DIN],  g_bf0l[HID * DIN];
__device__ int8_t g_bf1h[HID * HID],  g_bf1l[HID * HID];
__device__ int8_t g_bf2h[HID * HID],  g_bf2l[HID * HID];
__device__ int8_t g_bb2h[HID * HID],  g_bb2l[HID * HID];
__device__ int8_t g_bb1h[HID * HID],  g_bb1l[HID * HID];
__device__ int8_t g_bb0h[DIN * HID],  g_bb0l[DIN * HID];

// ---------------- helpers ----------------------------------------------------
__device__ __forceinline__ uint32_t s2u(const void* p) {
    uint32_t a;
    asm("{ .reg .u64 t; cvta.to.shared.u64 t, %1; cvt.u32.u64 %0, t; }"
        : "=r"(a) : "l"(p));
    return a;
}
__device__ __forceinline__ void cpa16(uint32_t dst, const void* src) {
    asm volatile("cp.async.cg.shared.global [%0], [%1], 16;" :: "r"(dst), "l"(src));
}
__device__ __forceinline__ void cp_commit() {
    asm volatile("cp.async.commit_group;" ::: "memory");
}
template <int N>
__device__ __forceinline__ void cp_wait() {
    asm volatile("cp.async.wait_group %0;" :: "n"(N) : "memory");
}
__device__ __forceinline__ void ldx4(uint32_t* r, uint32_t a) {
    asm volatile("ldmatrix.sync.aligned.m8n8.x4.shared.b16 {%0,%1,%2,%3}, [%4];"
                 : "=r"(r[0]), "=r"(r[1]), "=r"(r[2]), "=r"(r[3]) : "r"(a));
}
__device__ __forceinline__ void imma(int* c, const uint32_t* a, uint32_t b0,
                                     uint32_t b1) {
    asm volatile(
        "mma.sync.aligned.m16n8k32.row.col.s32.s8.s8.s32 "
        "{%0,%1,%2,%3}, {%4,%5,%6,%7}, {%8,%9}, {%0,%1,%2,%3};"
        : "+r"(c[0]), "+r"(c[1]), "+r"(c[2]), "+r"(c[3])
        : "r"(a[0]), "r"(a[1]), "r"(a[2]), "r"(a[3]), "r"(b0), "r"(b1));
}
// 15-bit split quantize: v*invS in [-16319,16319] -> hi,lo int8
__device__ __forceinline__ void q15(float v, float invS, int& qh, int& ql) {
    int q = __float2int_rn(v * invS);
    q = max(-16319, min(16319, q));
    qh = (q + 64) >> 7;
    ql = q - (qh << 7);
}
__device__ __forceinline__ uint16_t pack2(int a, int b) {
    return (uint16_t)((a & 0xff) | ((b & 0xff) << 8));
}
__device__ __forceinline__ float scale_of(const int* bits) {
    return __int_as_float(__ldg(bits)) * (1.f / 16319.f);
}

// ---------------- pre-pass kernels -------------------------------------------
__global__ void max_all(const float* __restrict__ x, const float* __restrict__ W0,
                        const float* __restrict__ W1, const float* __restrict__ W2,
                        const float* __restrict__ W3) {
    int seg = blockIdx.y;
    const float* p;
    int n, idx;
    switch (seg) {
        case 0: p = x;  n = BATCH * DIN; idx = 0; break;
        case 1: p = W0; n = DIN * HID;   idx = 1; break;
        case 2: p = W1; n = HID * HID;   idx = 2; break;
        case 3: p = W2; n = HID * HID;   idx = 3; break;
        default: p = W3; n = HID;        idx = 4; break;
    }
    float m = 0.f;
    for (int i = blockIdx.x * 256 + threadIdx.x; i < n; i += gridDim.x * 256)
        m = fmaxf(m, fabsf(p[i]));
    int mi = __reduce_max_sync(0xffffffff, __float_as_int(m));
    if ((threadIdx.x & 31) == 0) atomicMax(&g_maxbits[idx], mi);
}

__global__ void pack_x(const float* __restrict__ x) {
    float invS = 16319.f / __int_as_float(g_maxbits[0]);
    int t = blockIdx.x * 256 + threadIdx.x;
    if (t >= BATCH * DIN) return;
    int qh, ql;
    q15(x[t], invS, qh, ql);
    g_xh[t] = (int8_t)qh;
    g_xl[t] = (int8_t)ql;
}

// fused weight packing: blockIdx.y selects target
__global__ void pack_wall(const float* __restrict__ W0, const float* __restrict__ W1,
                          const float* __restrict__ W2) {
    int seg = blockIdx.y;
    const float* W;
    int8_t *dh, *dl;
    int N, K, midx, tr;
    switch (seg) {
        case 0: W = W0; dh = g_bf0h; dl = g_bf0l; N = HID; K = DIN; midx = 1; tr = 1; break;
        case 1: W = W1; dh = g_bf1h; dl = g_bf1l; N = HID; K = HID; midx = 2; tr = 1; break;
        case 2: W = W2; dh = g_bf2h; dl = g_bf2l; N = HID; K = HID; midx = 3; tr = 1; break;
        case 3: W = W2; dh = g_bb2h; dl = g_bb2l; N = HID; K = HID; midx = 3; tr = 0; break;
        case 4: W = W1; dh = g_bb1h; dl = g_bb1l; N = HID; K = HID; midx = 2; tr = 0; break;
        default: W = W0; dh = g_bb0h; dl = g_bb0l; N = DIN; K = HID; midx = 1; tr = 0; break;
    }
    float invS = 16319.f / __int_as_float(g_maxbits[midx]);
    int t = blockIdx.x * 256 + threadIdx.x;
    if (t >= N * K) return;
    int n = t / K, k = t % K;
    // tr: W stored [K][N] (in x out) -> dst[n][k]=W[k][n]; else W stored [N][K]
    float v = tr ? W[(size_t)k * N + n] : W[(size_t)n * K + k];
    int qh, ql;
    q15(v, invS, qh, ql);
    dh[t] = (int8_t)qh;
    dl[t] = (int8_t)ql;
}

__global__ void repack(const float* __restrict__ src, int8_t* __restrict__ dh,
                       int8_t* __restrict__ dl, int midx) {
    float invS = 16319.f / __int_as_float(g_maxbits[midx]);
    int t = blockIdx.x * 256 + threadIdx.x;
    if (t >= BATCH * HID) return;
    int qh, ql;
    q15(src[t], invS, qh, ql);
    dh[t] = (int8_t)qh;
    dl[t] = (int8_t)ql;
}

// ---------------- int8 IMMA GEMM, 3-pass 15-bit split ------------------------
// CTA 128 x NTILE, 512 threads. k-chunk = 64. acc = 16384*acc_hh + 128*acc_x.
template <int EPI, int NTILE>
__global__ void __launch_bounds__(512)
hnn_gemm_i8(const int8_t* __restrict__ Ah, const int8_t* __restrict__ Al,
            const int8_t* __restrict__ Bh, const int8_t* __restrict__ Bl,
            const int* sAbits, float sAconst, const int* sBbits,
            const int* oSbits,  // output quant max (nullptr -> unit scale 1/16319)
            const float* __restrict__ bias, const float* __restrict__ w3,
            const int8_t* __restrict__ Hh, const int8_t* __restrict__ Hl,
            int8_t* __restrict__ Oh, int8_t* __restrict__ Ol,
            float* __restrict__ Of, int* omax,
            float* __restrict__ Osym, int K, int NTOT) {
    constexpr int PITCH = 80;                  // 64 data + 16 pad bytes
    constexpr int ASZ = 128 * PITCH;
    constexpr int BSZ = NTILE * PITCH;
    constexpr int STAGE = 2 * ASZ + 2 * BSZ;
    constexpr int WN = NTILE / 32;
    constexpr int WM = 16 / WN;
    constexpr int MI = 128 / (WM * 16);

    extern __shared__ __align__(16) char smem[];
    const uint32_t sb = s2u(smem);

    const int tid = threadIdx.x;
    const int lane = tid & 31;
    const int w = tid >> 5;
    const int wm = w % WM, wn = w / WM;
    const int m0 = blockIdx.y * 128;
    const int n0 = blockIdx.x * NTILE;
    const int mbase = wm * (128 / WM);
    const int nbase = wn * 32;
    const int KC = K >> 6;

    int acch[MI][4][4], accx[MI][4][4];
#pragma unroll
    for (int i = 0; i < MI; i++)
#pragma unroll
        for (int j = 0; j < 4; j++)
#pragma unroll
            for (int e = 0; e < 4; e++) { acch[i][j][e] = 0; accx[i][j][e] = 0; }

    const int arow = tid >> 2, ac = tid & 3;

    auto load_chunk = [&](int cc, int st) {
        int k0 = cc << 6;
        uint32_t base = sb + st * STAGE;
        cpa16(base + arow * PITCH + ac * 16, Ah + (size_t)(m0 + arow) * K + k0 + ac * 16);
        cpa16(base + ASZ + arow * PITCH + ac * 16,
              Al + (size_t)(m0 + arow) * K + k0 + ac * 16);
        if (NTILE == 128 || tid < NTILE * 4) {
            cpa16(base + 2 * ASZ + arow * PITCH + ac * 16,
                  Bh + (size_t)(n0 + arow) * K + k0 + ac * 16);
            cpa16(base + 2 * ASZ + BSZ + arow * PITCH + ac * 16,
                  Bl + (size_t)(n0 + arow) * K + k0 + ac * 16);
        }
        cp_commit();
    };

    load_chunk(0, 0);
    if (KC > 1) load_chunk(1, 1);

    for (int i = 0; i < KC; i++) {
        if (i + 1 < KC) cp_wait<1>(); else cp_wait<0>();
        __syncthreads();
        if (i + 2 < KC) load_chunk(i + 2, (i + 2) % 3);

        uint32_t base = sb + (i % 3) * STAGE;
        uint32_t aBh = base, aBl = base + ASZ;
        uint32_t bBh = base + 2 * ASZ, bBl = bBh + BSZ;
#pragma unroll
        for (int ks = 0; ks < 2; ks++) {
            const uint32_t aoff =
                (uint32_t)(lane & 15) * PITCH + ks * 32 + ((lane >> 4) << 4);
            const uint32_t boff =
                (uint32_t)(((lane >> 3) & 1) * 8 + (lane & 7)) * PITCH + ks * 32 +
                ((lane >> 4) << 4);
            uint32_t aFh[MI][4], aFl[MI][4], bFh[2][4], bFl[2][4];
#pragma unroll
            for (int ii = 0; ii < MI; ii++) {
                ldx4(aFh[ii], aBh + (mbase + ii * 16) * PITCH + aoff);
                ldx4(aFl[ii], aBl + (mbase + ii * 16) * PITCH + aoff);
            }
#pragma unroll
            for (int g = 0; g < 2; g++) {
                ldx4(bFh[g], bBh + (nbase + g * 16) * PITCH + boff);
                ldx4(bFl[g], bBl + (nbase + g * 16) * PITCH + boff);
            }
#pragma unroll
            for (int ii = 0; ii < MI; ii++)
#pragma unroll
                for (int nj = 0; nj < 4; nj++) {
                    int g = nj >> 1, j = nj & 1;
                    imma(acch[ii][nj], aFh[ii], bFh[g][j], bFh[g][j + 2]);
                    imma(accx[ii][nj], aFh[ii], bFl[g][j], bFl[g][j + 2]);
                    imma(accx[ii][nj], aFl[ii], bFh[g][j], bFh[g][j + 2]);
                }
        }
    }

    // ---------------- epilogue ----------------
    const float Sa = sAbits ? scale_of(sAbits) : sAconst;
    const float Sb = scale_of(sBbits);
    const float S = Sa * Sb;
    const float invSo = oSbits ? 16319.f / __int_as_float(__ldg(oSbits)) : 16319.f;
    const int qr = lane >> 2, qc = lane & 3;
    float lmax = 0.f;
#pragma unroll
    for (int i = 0; i < MI; i++) {
#pragma unroll
        for (int nj = 0; nj < 4; nj++) {
            int n = n0 + nbase + nj * 8 + qc * 2;
#pragma unroll
            for (int h = 0; h < 2; h++) {
                int m = m0 + mbase + i * 16 + qr + h * 8;
                float v0 = S * (16384.f * (float)acch[i][nj][h * 2] +
                                128.f * (float)accx[i][nj][h * 2]);
                float v1 = S * (16384.f * (float)acch[i][nj][h * 2 + 1] +
                                128.f * (float)accx[i][nj][h * 2 + 1]);
                if constexpr (EPI == EPI_TANH) {
                    v0 = tanhf(v0 + __ldg(bias + n));
                    v1 = tanhf(v1 + __ldg(bias + n + 1));
                } else if constexpr (EPI == EPI_DA2) {
                    float t0 = tanhf(v0 + __ldg(bias + n));
                    float t1 = tanhf(v1 + __ldg(bias + n + 1));
                    v0 = __ldg(w3 + n) * (1.f - t0 * t0);
                    v1 = __ldg(w3 + n + 1) * (1.f - t1 * t1);
                } else if constexpr (EPI == EPI_MULT) {
                    size_t off = (size_t)m * NTOT + n;
                    uint16_t uh = *(const uint16_t*)(Hh + off);
                    uint16_t ul = *(const uint16_t*)(Hl + off);
                    float h0v = ((float)((int8_t)(uh & 0xff)) * 128.f +
                                 (float)((int8_t)(ul & 0xff))) * (1.f / 16319.f);
                    float h1v = ((float)((int8_t)(uh >> 8)) * 128.f +
                                 (float)((int8_t)(ul >> 8))) * (1.f / 16319.f);
                    v0 *= (1.f - h0v * h0v);
                    v1 *= (1.f - h1v * h1v);
                }
                if constexpr (EPI == EPI_SYMP) {
                    float sgn = (n >= 32) ? 1.f : -1.f;
                    *(float2*)(Osym + (size_t)m * 64 + (n ^ 32)) =
                        make_float2(sgn * v0, sgn * v1);
                } else if constexpr (EPI == EPI_MULT) {
                    *(float2*)(Of + (size_t)m * NTOT + n) = make_float2(v0, v1);
                    lmax = fmaxf(lmax, fmaxf(fabsf(v0), fabsf(v1)));
                } else {
                    int qh0, ql0, qh1, ql1;
                    q15(v0, invSo, qh0, ql0);
                    q15(v1, invSo, qh1, ql1);
                    size_t off = (size_t)m * NTOT + n;
                    *(uint16_t*)(Oh + off) = pack2(qh0, qh1);
                    *(uint16_t*)(Ol + off) = pack2(ql0, ql1);
                }
            }
        }
    }
    if constexpr (EPI == EPI_MULT) {
        int mi = __reduce_max_sync(0xffffffff, __float_as_int(lmax));
        if (lane == 0) atomicMax(omax, mi);
    }
}

// ---------------- host -------------------------------------------------------
extern "C" void kernel_launch(void* const* d_in, const int* in_sizes, int n_in,
                              void* d_out, int out_size) {
    (void)in_sizes; (void)n_in; (void)out_size;
    const float* x  = (const float*)d_in[1];
    const float* W0 = (const float*)d_in[2];
    const float* b0 = (const float*)d_in[3];
    const float* W1 = (const float*)d_in[4];
    const float* b1 = (const float*)d_in[5];
    const float* W2 = (const float*)d_in[6];
    const float* b2 = (const float*)d_in[7];
    const float* W3 = (const float*)d_in[8];
    float* out = (float*)d_out;

    int* mb;
    cudaGetSymbolAddress((void**)&mb, g_maxbits);
    int8_t *xh, *xl, *h0h, *h0l, *h1h, *h1l, *d2h, *d2l, *d1h, *d1l, *d0h, *d0l;
    float *d1f, *d0f;
    int8_t *bf0h, *bf0l, *bf1h, *bf1l, *bf2h, *bf2l, *bb2h, *bb2l, *bb1h, *bb1l, *bb0h, *bb0l;
    cudaGetSymbolAddress((void**)&xh, g_xh);   cudaGetSymbolAddress((void**)&xl, g_xl);
    cudaGetSymbolAddress((void**)&h0h, g_h0h); cudaGetSymbolAddress((void**)&h0l, g_h0l);
    cudaGetSymbolAddress((void**)&h1h, g_h1h); cudaGetSymbolAddress((void**)&h1l, g_h1l);
    cudaGetSymbolAddress((void**)&d2h, g_d2h); cudaGetSymbolAddress((void**)&d2l, g_d2l);
    cudaGetSymbolAddress((void**)&d1f, g_d1f);
    cudaGetSymbolAddress((void**)&d1h, g_d1h); cudaGetSymbolAddress((void**)&d1l, g_d1l);
    cudaGetSymbolAddress((void**)&d0f, g_d0f);
    cudaGetSymbolAddress((void**)&d0h, g_d0h); cudaGetSymbolAddress((void**)&d0l, g_d0l);
    cudaGetSymbolAddress((void**)&bf0h, g_bf0h); cudaGetSymbolAddress((void**)&bf0l, g_bf0l);
    cudaGetSymbolAddress((void**)&bf1h, g_bf1h); cudaGetSymbolAddress((void**)&bf1l, g_bf1l);
    cudaGetSymbolAddress((void**)&bf2h, g_bf2h); cudaGetSymbolAddress((void**)&bf2l, g_bf2l);
    cudaGetSymbolAddress((void**)&bb2h, g_bb2h); cudaGetSymbolAddress((void**)&bb2l, g_bb2l);
    cudaGetSymbolAddress((void**)&bb1h, g_bb1h); cudaGetSymbolAddress((void**)&bb1l, g_bb1l);
    cudaGetSymbolAddress((void**)&bb0h, g_bb0h); cudaGetSymbolAddress((void**)&bb0l, g_bb0l);

    // launches 0..2: maxes + packing
    max_all<<<dim3(256, 5), 256>>>(x, W0, W1, W2, W3);
    pack_x<<<(BATCH * DIN + 255) / 256, 256>>>(x);
    pack_wall<<<dim3(1024, 6), 256>>>(W0, W1, W2);

    constexpr int STG128 = 2 * 128 * 80 + 2 * 128 * 80;  // 20480+20480 = 40960
    constexpr int STG64  = 2 * 128 * 80 + 2 * 64 * 80;   // 30720
    constexpr int SM128 = 3 * STG128;  // 122880
    constexpr int SM64  = 3 * STG64;   // 92160
    cudaFuncSetAttribute(hnn_gemm_i8<EPI_TANH, 128>, cudaFuncAttributeMaxDynamicSharedMemorySize, SM128);
    cudaFuncSetAttribute(hnn_gemm_i8<EPI_DA2, 128>,  cudaFuncAttributeMaxDynamicSharedMemorySize, SM128);
    cudaFuncSetAttribute(hnn_gemm_i8<EPI_MULT, 128>, cudaFuncAttributeMaxDynamicSharedMemorySize, SM128);
    cudaFuncSetAttribute(hnn_gemm_i8<EPI_SYMP, 64>,  cudaFuncAttributeMaxDynamicSharedMemorySize, SM64);

    const float SH = 1.f / 16319.f;  // scale for tanh-bounded activations
    dim3 g(HID / 128, BATCH / 128);

    // 3: h0 = tanh(x@W0+b0)           A:x(max0)    B:bf0(max1)  out: int8 (unit bound)
    hnn_gemm_i8<EPI_TANH, 128><<<g, 512, SM128>>>(
        xh, xl, bf0h, bf0l, mb + 0, 0.f, mb + 1, nullptr, b0, nullptr,
        nullptr, nullptr, h0h, h0l, nullptr, nullptr, nullptr, DIN, HID);
    // 4: h1 = tanh(h0@W1+b1)
    hnn_gemm_i8<EPI_TANH, 128><<<g, 512, SM128>>>(
        h0h, h0l, bf1h, bf1l, nullptr, SH, mb + 2, nullptr, b1, nullptr,
        nullptr, nullptr, h1h, h1l, nullptr, nullptr, nullptr, HID, HID);
    // 5: d2 = W3*(1-tanh(h1@W2+b2)^2)  out scale bound = max|W3| (mb+4)
    hnn_gemm_i8<EPI_DA2, 128><<<g, 512, SM128>>>(
        h1h, h1l, bf2h, bf2l, nullptr, SH, mb + 3, mb + 4, b2, W3,
        nullptr, nullptr, d2h, d2l, nullptr, nullptr, nullptr, HID, HID);
    // 6: d1 = (d2@W2^T)*(1-h1^2) -> float + max (mb+5)
    hnn_gemm_i8<EPI_MULT, 128><<<g, 512, SM128>>>(
        d2h, d2l, bb2h, bb2l, mb + 4, 0.f, mb + 3, nullptr, nullptr, nullptr,
        h1h, h1l, nullptr, nullptr, d1f, mb + 5, nullptr, HID, HID);
    // 7: repack d1
    repack<<<(BATCH * HID + 255) / 256, 256>>>(d1f, d1h, d1l, 5);
    // 8: d0 = (d1@W1^T)*(1-h0^2) -> float + max (mb+6)
    hnn_gemm_i8<EPI_MULT, 128><<<g, 512, SM128>>>(
        d1h, d1l, bb1h, bb1l, mb + 5, 0.f, mb + 2, nullptr, nullptr, nullptr,
        h0h, h0l, nullptr, nullptr, d0f, mb + 6, nullptr, HID, HID);
    // 9: repack d0
    repack<<<(BATCH * HID + 255) / 256, 256>>>(d0f, d0h, d0l, 6);
    // 10: out = symplectic(d0@W0^T)
    hnn_gemm_i8<EPI_SYMP, 64><<<dim3(1, BATCH / 128), 512, SM64>>>(
        d0h, d0l, bb0h, bb0l, mb + 6, 0.f, mb + 1, nullptr, nullptr, nullptr,
        nullptr, nullptr, nullptr, nullptr, nullptr, nullptr, out, HID, DIN);
}

// round 9
// speedup vs baseline: 2.7395x; 2.7395x over previous
#include <cuda_runtime.h>
#include <cuda_bf16.h>
#include <stdint.h>
#include <math.h>

typedef __nv_bfloat16 bf16;

#define BATCH 65536
#define DIN   64
#define HID   512
#define MH    49664              // tensor-path rows (388*128)
#define MF    (BATCH - MH)       // fp32-path rows (124*128)

enum { EPI_TANH = 0, EPI_DA2 = 1, EPI_MULT = 2, EPI_SYMP = 3 };

// ---------------- scratch ----------------------------------------------------
__device__ bf16 g_a0h[(size_t)MH * DIN],  g_a0l[(size_t)MH * DIN];
__device__ bf16 g_h0h[(size_t)MH * HID],  g_h0l[(size_t)MH * HID];
__device__ bf16 g_h1h[(size_t)MH * HID],  g_h1l[(size_t)MH * HID];
__device__ bf16 g_d2h[(size_t)MH * HID],  g_d2l[(size_t)MH * HID];
__device__ bf16 g_d1h[(size_t)MH * HID],  g_d1l[(size_t)MH * HID];
__device__ bf16 g_d0h[(size_t)MH * HID],  g_d0l[(size_t)MH * HID];
__device__ bf16 g_bf0h[HID * DIN], g_bf0l[HID * DIN];
__device__ bf16 g_bf1h[HID * HID], g_bf1l[HID * HID];
__device__ bf16 g_bf2h[HID * HID], g_bf2l[HID * HID];
__device__ bf16 g_bb2h[HID * HID], g_bb2l[HID * HID];
__device__ bf16 g_bb1h[HID * HID], g_bb1l[HID * HID];
__device__ bf16 g_bb0h[DIN * HID], g_bb0l[DIN * HID];
__device__ float g_fh0[(size_t)MF * HID];
__device__ float g_fh1[(size_t)MF * HID];
__device__ float g_fda[(size_t)MF * HID];
__device__ float g_fdb[(size_t)MF * HID];
__device__ float g_W1t[HID * HID];
__device__ float g_W2t[HID * HID];
__device__ float g_W0t[HID * DIN];

// ---------------- helpers ----------------------------------------------------
__device__ __forceinline__ uint32_t s2u(const void* p) {
    uint32_t a;
    asm("{ .reg .u64 t; cvta.to.shared.u64 t, %1; cvt.u32.u64 %0, t; }"
        : "=r"(a) : "l"(p));
    return a;
}
__device__ __forceinline__ void split_bf(float v, uint16_t& h, uint16_t& l) {
    bf16 hb = __float2bfloat16(v);
    bf16 lb = __float2bfloat16(v - __bfloat162float(hb));
    h = __bfloat16_as_ushort(hb);
    l = __bfloat16_as_ushort(lb);
}
__device__ __forceinline__ void cpa16(uint32_t dst, const void* src) {
    asm volatile("cp.async.cg.shared.global [%0], [%1], 16;" :: "r"(dst), "l"(src));
}
__device__ __forceinline__ void cp_commit() {
    asm volatile("cp.async.commit_group;" ::: "memory");
}
template <int N>
__device__ __forceinline__ void cp_wait() {
    asm volatile("cp.async.wait_group %0;" :: "n"(N) : "memory");
}
__device__ __forceinline__ void ldx4(uint32_t* r, uint32_t a) {
    asm volatile("ldmatrix.sync.aligned.m8n8.x4.shared.b16 {%0,%1,%2,%3}, [%4];"
                 : "=r"(r[0]), "=r"(r[1]), "=r"(r[2]), "=r"(r[3]) : "r"(a));
}
__device__ __forceinline__ void mma16816(float* c, const uint32_t* a,
                                         uint32_t b0, uint32_t b1) {
    asm volatile(
        "mma.sync.aligned.m16n8k16.row.col.f32.bf16.bf16.f32 "
        "{%0,%1,%2,%3}, {%4,%5,%6,%7}, {%8,%9}, {%0,%1,%2,%3};"
        : "+f"(c[0]), "+f"(c[1]), "+f"(c[2]), "+f"(c[3])
        : "r"(a[0]), "r"(a[1]), "r"(a[2]), "r"(a[3]), "r"(b0), "r"(b1));
}

// ---------------- H prepass --------------------------------------------------
__global__ void convert_x(const float* __restrict__ x, bf16* __restrict__ hi,
                          bf16* __restrict__ lo, int n) {
    int t = blockIdx.x * 256 + threadIdx.x;
    if (t >= n) return;
    uint16_t h, l;
    split_bf(x[t], h, l);
    hi[t] = __ushort_as_bfloat16(h);
    lo[t] = __ushort_as_bfloat16(l);
}
template <bool TR>
__global__ void pack_w(const float* __restrict__ W, int N, int K,
                       bf16* __restrict__ hi, bf16* __restrict__ lo) {
    int t = blockIdx.x * 256 + threadIdx.x;
    if (t >= N * K) return;
    int n = t / K, k = t % K;
    float v = TR ? W[(size_t)k * N + n] : W[(size_t)n * K + k];
    uint16_t h, l;
    split_bf(v, h, l);
    hi[t] = __ushort_as_bfloat16(h);
    lo[t] = __ushort_as_bfloat16(l);
}

// ---------------- H: HMMA GEMM (256 thr, 3-stage, shared-tile 3xBF16) --------
template <int EPI, int NTILE>
__global__ void __launch_bounds__(256, 2)
hnn_gemm(const bf16* __restrict__ Ah, const bf16* __restrict__ Al,
         const bf16* __restrict__ Bh, const bf16* __restrict__ Bl,
         const float* __restrict__ bias, const float* __restrict__ w3,
         const bf16* __restrict__ Hh, const bf16* __restrict__ Hl,
         bf16* __restrict__ Oh, bf16* __restrict__ Ol,
         float* __restrict__ Osym, int K, int NTOT) {
    constexpr int PITCH = 80;
    constexpr int ASZ = 128 * PITCH;
    constexpr int BSZ = NTILE * PITCH;
    constexpr int STAGE = 2 * ASZ + 2 * BSZ;
    constexpr int WN = NTILE / 32;
    constexpr int WM = 8 / WN;
    constexpr int MI = 128 / (WM * 16);
    extern __shared__ __align__(16) char smem[];
    const uint32_t sb = s2u(smem);

    const int tid = threadIdx.x;
    const int lane = tid & 31;
    const int w = tid >> 5;
    const int wm = w % WM, wn = w / WM;
    const int m0 = blockIdx.y * 128;
    const int n0 = blockIdx.x * NTILE;
    const int mbase = wm * (128 / WM);
    const int nbase = wn * 32;
    const int KC = K >> 5;

    float acc[MI][4][4];
#pragma unroll
    for (int i = 0; i < MI; i++)
#pragma unroll
        for (int j = 0; j < 4; j++)
#pragma unroll
            for (int e = 0; e < 4; e++) acc[i][j][e] = 0.f;

    auto load_chunk = [&](int cc, int st) {
        int k0 = cc << 5;
        uint32_t base = sb + st * STAGE;
        int r = tid >> 2, c = tid & 3;
#pragma unroll
        for (int i = 0; i < 2; i++) {
            int rr = r + i * 64;
            cpa16(base + rr * PITCH + c * 16, Ah + (size_t)(m0 + rr) * K + k0 + c * 8);
            cpa16(base + ASZ + rr * PITCH + c * 16,
                  Al + (size_t)(m0 + rr) * K + k0 + c * 8);
        }
#pragma unroll
        for (int i = 0; i < NTILE / 64; i++) {
            int rr = r + i * 64;
            cpa16(base + 2 * ASZ + rr * PITCH + c * 16,
                  Bh + (size_t)(n0 + rr) * K + k0 + c * 8);
            cpa16(base + 2 * ASZ + BSZ + rr * PITCH + c * 16,
                  Bl + (size_t)(n0 + rr) * K + k0 + c * 8);
        }
        cp_commit();
    };

    load_chunk(0, 0);
    if (KC > 1) load_chunk(1, 1);
    for (int i = 0; i < KC; i++) {
        if (i + 1 < KC) cp_wait<1>(); else cp_wait<0>();
        __syncthreads();
        if (i + 2 < KC) load_chunk(i + 2, (i + 2) % 3);
        uint32_t base = sb + (i % 3) * STAGE;
        uint32_t aBh = base, aBl = base + ASZ;
        uint32_t bBh = base + 2 * ASZ, bBl = bBh + BSZ;
#pragma unroll
        for (int ks = 0; ks < 2; ks++) {
            const uint32_t aoff = (lane & 15) * PITCH + ks * 32 + ((lane >> 4) << 4);
            const uint32_t boff =
                (((lane >> 4) << 3) + (lane & 7)) * PITCH + ks * 32 +
                (((lane >> 3) & 1) << 4);
            uint32_t aFh[MI][4], aFl[MI][4], bFh[2][4], bFl[2][4];
#pragma unroll
            for (int ii = 0; ii < MI; ii++)
                ldx4(aFh[ii], aBh + (mbase + ii * 16) * PITCH + aoff);
#pragma unroll
            for (int j = 0; j < 2; j++)
                ldx4(bFh[j], bBh + (nbase + j * 16) * PITCH + boff);
#pragma unroll
            for (int ii = 0; ii < MI; ii++)
#pragma unroll
                for (int nj = 0; nj < 4; nj++)
                    mma16816(acc[ii][nj], aFh[ii], bFh[nj >> 1][(nj & 1) * 2],
                             bFh[nj >> 1][(nj & 1) * 2 + 1]);
#pragma unroll
            for (int ii = 0; ii < MI; ii++)
                ldx4(aFl[ii], aBl + (mbase + ii * 16) * PITCH + aoff);
#pragma unroll
            for (int ii = 0; ii < MI; ii++)
#pragma unroll
                for (int nj = 0; nj < 4; nj++)
                    mma16816(acc[ii][nj], aFl[ii], bFh[nj >> 1][(nj & 1) * 2],
                             bFh[nj >> 1][(nj & 1) * 2 + 1]);
#pragma unroll
            for (int j = 0; j < 2; j++)
                ldx4(bFl[j], bBl + (nbase + j * 16) * PITCH + boff);
#pragma unroll
            for (int ii = 0; ii < MI; ii++)
#pragma unroll
                for (int nj = 0; nj < 4; nj++)
                    mma16816(acc[ii][nj], aFh[ii], bFl[nj >> 1][(nj & 1) * 2],
                             bFl[nj >> 1][(nj & 1) * 2 + 1]);
        }
    }

    const int qr = lane >> 2, qc = lane & 3;
#pragma unroll
    for (int i = 0; i < MI; i++) {
#pragma unroll
        for (int nj = 0; nj < 4; nj++) {
            int n = n0 + nbase + nj * 8 + qc * 2;
#pragma unroll
            for (int h = 0; h < 2; h++) {
                int m = m0 + mbase + i * 16 + qr + h * 8;
                float v0 = acc[i][nj][h * 2], v1 = acc[i][nj][h * 2 + 1];
                if constexpr (EPI == EPI_TANH) {
                    v0 = tanhf(v0 + __ldg(bias + n));
                    v1 = tanhf(v1 + __ldg(bias + n + 1));
                } else if constexpr (EPI == EPI_DA2) {
                    float t0 = tanhf(v0 + __ldg(bias + n));
                    float t1 = tanhf(v1 + __ldg(bias + n + 1));
                    v0 = __ldg(w3 + n) * (1.f - t0 * t0);
                    v1 = __ldg(w3 + n + 1) * (1.f - t1 * t1);
                } else if constexpr (EPI == EPI_MULT) {
                    size_t off = ((size_t)m * NTOT + n) * 2;
                    uint32_t uh = *(const uint32_t*)((const char*)Hh + off);
                    uint32_t ul = *(const uint32_t*)((const char*)Hl + off);
                    float h0 = __bfloat162float(__ushort_as_bfloat16((uint16_t)uh)) +
                               __bfloat162float(__ushort_as_bfloat16((uint16_t)ul));
                    float h1 = __bfloat162float(__ushort_as_bfloat16((uint16_t)(uh >> 16))) +
                               __bfloat162float(__ushort_as_bfloat16((uint16_t)(ul >> 16)));
                    v0 *= (1.f - h0 * h0);
                    v1 *= (1.f - h1 * h1);
                }
                if constexpr (EPI == EPI_SYMP) {
                    float sgn = (n >= 32) ? 1.f : -1.f;
                    *(float2*)(Osym + (size_t)m * 64 + (n ^ 32)) =
                        make_float2(sgn * v0, sgn * v1);
                } else {
                    uint16_t h0, l0, h1, l1;
                    split_bf(v0, h0, l0);
                    split_bf(v1, h1, l1);
                    size_t off = ((size_t)m * NTOT + n) * 2;
                    *(uint32_t*)((char*)Oh + off) = (uint32_t)h0 | ((uint32_t)h1 << 16);
                    *(uint32_t*)((char*)Ol + off) = (uint32_t)l0 | ((uint32_t)l1 << 16);
                }
            }
        }
    }
}

// ---------------- F: fp32 SGEMM path (R0, proven) ----------------------------
__global__ void transpose_k(const float* __restrict__ in, float* __restrict__ out,
                            int R, int C) {
    __shared__ float tile[32][33];
    int c0 = blockIdx.x * 32, r0 = blockIdx.y * 32;
    int tx = threadIdx.x, ty = threadIdx.y;
#pragma unroll
    for (int i = 0; i < 32; i += 8) {
        int r = r0 + ty + i, c = c0 + tx;
        if (r < R && c < C) tile[ty + i][tx] = in[(size_t)r * C + c];
    }
    __syncthreads();
#pragma unroll
    for (int i = 0; i < 32; i += 8) {
        int r = c0 + ty + i, c = r0 + tx;
        if (r < C && c < R) out[(size_t)r * R + c] = tile[tx][ty + i];
    }
}

template <int BM, int BN, int BK, int TM, int TN, int EPI>
__global__ void __launch_bounds__((BM / TM) * (BN / TN), 2)
fgemm(const float* __restrict__ A, const float* __restrict__ Bm,
      float* __restrict__ C, const float* __restrict__ bias,
      const float* __restrict__ w3, const float* __restrict__ elem,
      int M, int N, int K) {
    constexpr int NT = (BM / TM) * (BN / TN);
    __shared__ float As[BK][BM];
    __shared__ float Bs[BK][BN];
    const int m0 = blockIdx.y * BM, n0 = blockIdx.x * BN;
    const int tid = threadIdx.x;
    const int tidm = tid / (BN / TN);
    const int tidn = tid % (BN / TN);
    float acc[TM][TN];
#pragma unroll
    for (int i = 0; i < TM; i++)
#pragma unroll
        for (int j = 0; j < TN; j++) acc[i][j] = 0.f;
    for (int k0 = 0; k0 < K; k0 += BK) {
#pragma unroll
        for (int f = tid; f < BM * BK / 4; f += NT) {
            int row = f / (BK / 4);
            int k4 = (f % (BK / 4)) * 4;
            float4 v = *(const float4*)(A + (size_t)(m0 + row) * K + k0 + k4);
            As[k4 + 0][row] = v.x;
            As[k4 + 1][row] = v.y;
            As[k4 + 2][row] = v.z;
            As[k4 + 3][row] = v.w;
        }
#pragma unroll
        for (int f = tid; f < BK * BN / 4; f += NT) {
            int kr = f / (BN / 4);
            int n4 = (f % (BN / 4)) * 4;
            *(float4*)&Bs[kr][n4] = *(const float4*)(Bm + (size_t)(k0 + kr) * N + n0 + n4);
        }
        __syncthreads();
#pragma unroll
        for (int k = 0; k < BK; k++) {
            float a[TM], b[TN];
#pragma unroll
            for (int v = 0; v < TM; v += 4)
                *(float4*)&a[v] = *(const float4*)&As[k][tidm * TM + v];
#pragma unroll
            for (int v = 0; v < TN; v += 4)
                *(float4*)&b[v] = *(const float4*)&Bs[k][tidn * TN + v];
#pragma unroll
            for (int i = 0; i < TM; i++)
#pragma unroll
                for (int j = 0; j < TN; j++) acc[i][j] += a[i] * b[j];
        }
        __syncthreads();
    }
#pragma unroll
    for (int i = 0; i < TM; i++) {
        int m = m0 + tidm * TM + i;
#pragma unroll
        for (int j = 0; j < TN; j++) {
            int n = n0 + tidn * TN + j;
            float v = acc[i][j];
            if constexpr (EPI == EPI_TANH) {
                C[(size_t)m * N + n] = tanhf(v + bias[n]);
            } else if constexpr (EPI == EPI_DA2) {
                float t = tanhf(v + bias[n]);
                C[(size_t)m * N + n] = w3[n] * (1.f - t * t);
            } else if constexpr (EPI == EPI_MULT) {
                float e = elem[(size_t)m * N + n];
                C[(size_t)m * N + n] = v * (1.f - e * e);
            } else {
                int oc = (n + 32) & 63;
                float s = (n >= 32) ? 1.f : -1.f;
                C[(size_t)m * 64 + oc] = s * v;
            }
        }
    }
}

// ---------------- host -------------------------------------------------------
extern "C" void kernel_launch(void* const* d_in, const int* in_sizes, int n_in,
                              void* d_out, int out_size) {
    (void)in_sizes; (void)n_in; (void)out_size;
    const float* x  = (const float*)d_in[1];
    const float* W0 = (const float*)d_in[2];
    const float* b0 = (const float*)d_in[3];
    const float* W1 = (const float*)d_in[4];
    const float* b1 = (const float*)d_in[5];
    const float* W2 = (const float*)d_in[6];
    const float* b2 = (const float*)d_in[7];
    const float* W3 = (const float*)d_in[8];
    float* out = (float*)d_out;

    bf16 *a0h, *a0l, *h0h, *h0l, *h1h, *h1l, *d2h, *d2l, *d1h, *d1l, *d0h, *d0l;
    bf16 *bf0h, *bf0l, *bf1h, *bf1l, *bf2h, *bf2l, *bb2h, *bb2l, *bb1h, *bb1l, *bb0h, *bb0l;
    float *fh0, *fh1, *fda, *fdb, *W1t, *W2t, *W0t;
    cudaGetSymbolAddress((void**)&a0h, g_a0h);  cudaGetSymbolAddress((void**)&a0l, g_a0l);
    cudaGetSymbolAddress((void**)&h0h, g_h0h);  cudaGetSymbolAddress((void**)&h0l, g_h0l);
    cudaGetSymbolAddress((void**)&h1h, g_h1h);  cudaGetSymbolAddress((void**)&h1l, g_h1l);
    cudaGetSymbolAddress((void**)&d2h, g_d2h);  cudaGetSymbolAddress((void**)&d2l, g_d2l);
    cudaGetSymbolAddress((void**)&d1h, g_d1h);  cudaGetSymbolAddress((void**)&d1l, g_d1l);
    cudaGetSymbolAddress((void**)&d0h, g_d0h);  cudaGetSymbolAddress((void**)&d0l, g_d0l);
    cudaGetSymbolAddress((void**)&bf0h, g_bf0h); cudaGetSymbolAddress((void**)&bf0l, g_bf0l);
    cudaGetSymbolAddress((void**)&bf1h, g_bf1h); cudaGetSymbolAddress((void**)&bf1l, g_bf1l);
    cudaGetSymbolAddress((void**)&bf2h, g_bf2h); cudaGetSymbolAddress((void**)&bf2l, g_bf2l);
    cudaGetSymbolAddress((void**)&bb2h, g_bb2h); cudaGetSymbolAddress((void**)&bb2l, g_bb2l);
    cudaGetSymbolAddress((void**)&bb1h, g_bb1h); cudaGetSymbolAddress((void**)&bb1l, g_bb1l);
    cudaGetSymbolAddress((void**)&bb0h, g_bb0h); cudaGetSymbolAddress((void**)&bb0l, g_bb0l);
    cudaGetSymbolAddress((void**)&fh0, g_fh0);  cudaGetSymbolAddress((void**)&fh1, g_fh1);
    cudaGetSymbolAddress((void**)&fda, g_fda);  cudaGetSymbolAddress((void**)&fdb, g_fdb);
    cudaGetSymbolAddress((void**)&W1t, g_W1t);  cudaGetSymbolAddress((void**)&W2t, g_W2t);
    cudaGetSymbolAddress((void**)&W0t, g_W0t);

    cudaStream_t s2;
    cudaStreamCreateWithFlags(&s2, cudaStreamNonBlocking);
    cudaEvent_t e1, e2;
    cudaEventCreateWithFlags(&e1, cudaEventDisableTiming);
    cudaEventCreateWithFlags(&e2, cudaEventDisableTiming);
    cudaEventRecord(e1, 0);
    cudaStreamWaitEvent(s2, e1, 0);

    // ---- F chain on s2 (rows [MH, BATCH)) ----
    const float* xF = x + (size_t)MH * DIN;
    float* outF = out + (size_t)MH * 64;
    dim3 tb(32, 8);
    transpose_k<<<dim3(HID / 32, HID / 32), tb, 0, s2>>>(W1, W1t, HID, HID);
    transpose_k<<<dim3(HID / 32, HID / 32), tb, 0, s2>>>(W2, W2t, HID, HID);
    transpose_k<<<dim3(HID / 32, 2), tb, 0, s2>>>(W0, W0t, DIN, HID);
    dim3 gf(HID / 128, MF / 128);
    fgemm<128, 128, 16, 8, 8, EPI_TANH><<<gf, 256, 0, s2>>>(
        xF, W0, fh0, b0, nullptr, nullptr, MF, HID, DIN);
    fgemm<128, 128, 16, 8, 8, EPI_TANH><<<gf, 256, 0, s2>>>(
        fh0, W1, fh1, b1, nullptr, nullptr, MF, HID, HID);
    fgemm<128, 128, 16, 8, 8, EPI_DA2><<<gf, 256, 0, s2>>>(
        fh1, W2, fda, b2, W3, nullptr, MF, HID, HID);
    fgemm<128, 128, 16, 8, 8, EPI_MULT><<<gf, 256, 0, s2>>>(
        fda, W2t, fdb, nullptr, nullptr, fh1, MF, HID, HID);
    fgemm<128, 128, 16, 8, 8, EPI_MULT><<<gf, 256, 0, s2>>>(
        fdb, W1t, fda, nullptr, nullptr, fh0, MF, HID, HID);
    fgemm<128, 64, 16, 8, 4, EPI_SYMP><<<dim3(1, MF / 128), 256, 0, s2>>>(
        fda, W0t, outF, nullptr, nullptr, nullptr, MF, DIN, HID);
    cudaEventRecord(e2, s2);

    // ---- H chain on default stream (rows [0, MH)) ----
    convert_x<<<(MH * DIN + 255) / 256, 256>>>(x, a0h, a0l, MH * DIN);
    pack_w<true><<<(HID * DIN + 255) / 256, 256>>>(W0, HID, DIN, bf0h, bf0l);
    pack_w<true><<<(HID * HID + 255) / 256, 256>>>(W1, HID, HID, bf1h, bf1l);
    pack_w<true><<<(HID * HID + 255) / 256, 256>>>(W2, HID, HID, bf2h, bf2l);
    pack_w<false><<<(HID * HID + 255) / 256, 256>>>(W2, HID, HID, bb2h, bb2l);
    pack_w<false><<<(HID * HID + 255) / 256, 256>>>(W1, HID, HID, bb1h, bb1l);
    pack_w<false><<<(DIN * HID + 255) / 256, 256>>>(W0, DIN, HID, bb0h, bb0l);

    constexpr int SM128 = 3 * (4 * 128 * 80);                 // 122880
    constexpr int SM64  = 3 * (2 * 128 * 80 + 2 * 64 * 80);   // 92160
    cudaFuncSetAttribute(hnn_gemm<EPI_TANH, 128>, cudaFuncAttributeMaxDynamicSharedMemorySize, SM128);
    cudaFuncSetAttribute(hnn_gemm<EPI_DA2, 128>,  cudaFuncAttributeMaxDynamicSharedMemorySize, SM128);
    cudaFuncSetAttribute(hnn_gemm<EPI_MULT, 128>, cudaFuncAttributeMaxDynamicSharedMemorySize, SM128);
    cudaFuncSetAttribute(hnn_gemm<EPI_SYMP, 64>,  cudaFuncAttributeMaxDynamicSharedMemorySize, SM64);

    dim3 gh(HID / 128, MH / 128);
    hnn_gemm<EPI_TANH, 128><<<gh, 256, SM128>>>(a0h, a0l, bf0h, bf0l, b0, nullptr,
                                                nullptr, nullptr, h0h, h0l, nullptr, DIN, HID);
    hnn_gemm<EPI_TANH, 128><<<gh, 256, SM128>>>(h0h, h0l, bf1h, bf1l, b1, nullptr,
                                                nullptr, nullptr, h1h, h1l, nullptr, HID, HID);
    hnn_gemm<EPI_DA2, 128><<<gh, 256, SM128>>>(h1h, h1l, bf2h, bf2l, b2, W3,
                                               nullptr, nullptr, d2h, d2l, nullptr, HID, HID);
    hnn_gemm<EPI_MULT, 128><<<gh, 256, SM128>>>(d2h, d2l, bb2h, bb2l, nullptr, nullptr,
                                                h1h, h1l, d1h, d1l, nullptr, HID, HID);
    hnn_gemm<EPI_MULT, 128><<<gh, 256, SM128>>>(d1h, d1l, bb1h, bb1l, nullptr, nullptr,
                                                h0h, h0l, d0h, d0l, nullptr, HID, HID);
    hnn_gemm<EPI_SYMP, 64><<<dim3(1, MH / 128), 256, SM64>>>(
        d0h, d0l, bb0h, bb0l, nullptr, nullptr, nullptr, nullptr,
        nullptr, nullptr, out, HID, DIN);

    cudaStreamWaitEvent(0, e2, 0);
    cudaEventDestroy(e1);
    cudaEventDestroy(e2);
    cudaStreamDestroy(s2);
}

// round 11
// speedup vs baseline: 3.2756x; 1.1957x over previous
#include <cuda_runtime.h>
#include <cuda_bf16.h>
#include <stdint.h>
#include <math.h>

typedef __nv_bfloat16 bf16;

#define BATCH 65536
#define DIN   64
#define HID   512
#define MH    57344              // tensor-path rows (448*128)
#define MF    (BATCH - MH)       // fp32-path rows (8192 = 64*128)

enum { EPI_TANH = 0, EPI_DA2 = 1, EPI_MULT = 2, EPI_SYMP = 3 };

// ---------------- scratch ----------------------------------------------------
__device__ bf16 g_a0h[(size_t)MH * DIN],  g_a0l[(size_t)MH * DIN];
__device__ bf16 g_h0h[(size_t)MH * HID],  g_h0l[(size_t)MH * HID];
__device__ bf16 g_h1h[(size_t)MH * HID],  g_h1l[(size_t)MH * HID];
__device__ bf16 g_d2h[(size_t)MH * HID],  g_d2l[(size_t)MH * HID];
__device__ bf16 g_d1h[(size_t)MH * HID],  g_d1l[(size_t)MH * HID];
__device__ bf16 g_d0h[(size_t)MH * HID],  g_d0l[(size_t)MH * HID];
__device__ bf16 g_bf0h[HID * DIN], g_bf0l[HID * DIN];
__device__ bf16 g_bf1h[HID * HID], g_bf1l[HID * HID];
__device__ bf16 g_bf2h[HID * HID], g_bf2l[HID * HID];
__device__ bf16 g_bb2h[HID * HID], g_bb2l[HID * HID];
__device__ bf16 g_bb1h[HID * HID], g_bb1l[HID * HID];
__device__ bf16 g_bb0h[DIN * HID], g_bb0l[DIN * HID];
__device__ float g_fh0[(size_t)MF * HID];
__device__ float g_fh1[(size_t)MF * HID];
__device__ float g_fda[(size_t)MF * HID];
__device__ float g_fdb[(size_t)MF * HID];
__device__ float g_W1t[HID * HID];
__device__ float g_W2t[HID * HID];
__device__ float g_W0t[HID * DIN];

// ---------------- helpers ----------------------------------------------------
__device__ __forceinline__ uint32_t s2u(const void* p) {
    uint32_t a;
    asm("{ .reg .u64 t; cvta.to.shared.u64 t, %1; cvt.u32.u64 %0, t; }"
        : "=r"(a) : "l"(p));
    return a;
}
__device__ __forceinline__ void split_bf(float v, uint16_t& h, uint16_t& l) {
    bf16 hb = __float2bfloat16(v);
    bf16 lb = __float2bfloat16(v - __bfloat162float(hb));
    h = __bfloat16_as_ushort(hb);
    l = __bfloat16_as_ushort(lb);
}
__device__ __forceinline__ void cpa16(uint32_t dst, const void* src) {
    asm volatile("cp.async.cg.shared.global [%0], [%1], 16;" :: "r"(dst), "l"(src));
}
__device__ __forceinline__ void cp_commit() {
    asm volatile("cp.async.commit_group;" ::: "memory");
}
template <int N>
__device__ __forceinline__ void cp_wait() {
    asm volatile("cp.async.wait_group %0;" :: "n"(N) : "memory");
}
__device__ __forceinline__ void ldx4(uint32_t* r, uint32_t a) {
    asm volatile("ldmatrix.sync.aligned.m8n8.x4.shared.b16 {%0,%1,%2,%3}, [%4];"
                 : "=r"(r[0]), "=r"(r[1]), "=r"(r[2]), "=r"(r[3]) : "r"(a));
}
__device__ __forceinline__ void mma16816(float* c, const uint32_t* a,
                                         uint32_t b0, uint32_t b1) {
    asm volatile(
        "mma.sync.aligned.m16n8k16.row.col.f32.bf16.bf16.f32 "
        "{%0,%1,%2,%3}, {%4,%5,%6,%7}, {%8,%9}, {%0,%1,%2,%3};"
        : "+f"(c[0]), "+f"(c[1]), "+f"(c[2]), "+f"(c[3])
        : "r"(a[0]), "r"(a[1]), "r"(a[2]), "r"(a[3]), "r"(b0), "r"(b1));
}

// ---------------- H prepass --------------------------------------------------
__global__ void convert_x(const float* __restrict__ x, bf16* __restrict__ hi,
                          bf16* __restrict__ lo, int n) {
    int t = blockIdx.x * 256 + threadIdx.x;
    if (t >= n) return;
    uint16_t h, l;
    split_bf(x[t], h, l);
    hi[t] = __ushort_as_bfloat16(h);
    lo[t] = __ushort_as_bfloat16(l);
}
template <bool TR>
__global__ void pack_w(const float* __restrict__ W, int N, int K,
                       bf16* __restrict__ hi, bf16* __restrict__ lo) {
    int t = blockIdx.x * 256 + threadIdx.x;
    if (t >= N * K) return;
    int n = t / K, k = t % K;
    float v = TR ? W[(size_t)k * N + n] : W[(size_t)n * K + k];
    uint16_t h, l;
    split_bf(v, h, l);
    hi[t] = __ushort_as_bfloat16(h);
    lo[t] = __ushort_as_bfloat16(l);
}

// ---------------- H: HMMA GEMM (512 thr, 3-stage, shared-tile 3xBF16) --------
// __launch_bounds__(640) caps regs at 102 so an F CTA's regs fit alongside.
template <int EPI, int NTILE>
__global__ void __launch_bounds__(640)
hnn_gemm(const bf16* __restrict__ Ah, const bf16* __restrict__ Al,
         const bf16* __restrict__ Bh, const bf16* __restrict__ Bl,
         const float* __restrict__ bias, const float* __restrict__ w3,
         const bf16* __restrict__ Hh, const bf16* __restrict__ Hl,
         bf16* __restrict__ Oh, bf16* __restrict__ Ol,
         float* __restrict__ Osym, int K, int NTOT) {
    constexpr int PITCH = 80;
    constexpr int ASZ = 128 * PITCH;
    constexpr int BSZ = NTILE * PITCH;
    constexpr int STAGE = 2 * ASZ + 2 * BSZ;
    constexpr int WN = NTILE / 32;
    constexpr int WM = 16 / WN;
    constexpr int MI = 128 / (WM * 16);
    extern __shared__ __align__(16) char smem[];
    const uint32_t sb = s2u(smem);

    const int tid = threadIdx.x;
    const int lane = tid & 31;
    const int w = tid >> 5;
    const int wm = w % WM, wn = w / WM;
    const int m0 = blockIdx.y * 128;
    const int n0 = blockIdx.x * NTILE;
    const int mbase = wm * (128 / WM);
    const int nbase = wn * 32;
    const int KC = K >> 5;

    float acc[MI][4][4];
#pragma unroll
    for (int i = 0; i < MI; i++)
#pragma unroll
        for (int j = 0; j < 4; j++)
#pragma unroll
            for (int e = 0; e < 4; e++) acc[i][j][e] = 0.f;

    const int arow = tid >> 2, ac = tid & 3;

    auto load_chunk = [&](int cc, int st) {
        int k0 = cc << 5;
        uint32_t base = sb + st * STAGE;
        cpa16(base + arow * PITCH + ac * 16, Ah + (size_t)(m0 + arow) * K + k0 + ac * 8);
        cpa16(base + ASZ + arow * PITCH + ac * 16,
              Al + (size_t)(m0 + arow) * K + k0 + ac * 8);
        if (NTILE == 128 || tid < NTILE * 4) {
            cpa16(base + 2 * ASZ + arow * PITCH + ac * 16,
                  Bh + (size_t)(n0 + arow) * K + k0 + ac * 8);
            cpa16(base + 2 * ASZ + BSZ + arow * PITCH + ac * 16,
                  Bl + (size_t)(n0 + arow) * K + k0 + ac * 8);
        }
        cp_commit();
    };

    load_chunk(0, 0);
    if (KC > 1) load_chunk(1, 1);

    for (int i = 0; i < KC; i++) {
        if (i + 1 < KC) cp_wait<1>(); else cp_wait<0>();
        __syncthreads();
        if (i + 2 < KC) load_chunk(i + 2, (i + 2) % 3);

        uint32_t base = sb + (i % 3) * STAGE;
        uint32_t aBh = base, aBl = base + ASZ;
        uint32_t bBh = base + 2 * ASZ, bBl = bBh + BSZ;
#pragma unroll
        for (int ks = 0; ks < 2; ks++) {
            const uint32_t aoff = (lane & 15) * PITCH + ks * 32 + ((lane >> 4) << 4);
            const uint32_t boff =
                (((lane >> 4) << 3) + (lane & 7)) * PITCH + ks * 32 +
                (((lane >> 3) & 1) << 4);
            uint32_t aFh[MI][4], aFl[MI][4], bFh[2][4], bFl[2][4];
#pragma unroll
            for (int ii = 0; ii < MI; ii++)
                ldx4(aFh[ii], aBh + (mbase + ii * 16) * PITCH + aoff);
#pragma unroll
            for (int j = 0; j < 2; j++)
                ldx4(bFh[j], bBh + (nbase + j * 16) * PITCH + boff);
#pragma unroll
            for (int ii = 0; ii < MI; ii++)
#pragma unroll
                for (int nj = 0; nj < 4; nj++)
                    mma16816(acc[ii][nj], aFh[ii], bFh[nj >> 1][(nj & 1) * 2],
                             bFh[nj >> 1][(nj & 1) * 2 + 1]);
#pragma unroll
            for (int ii = 0; ii < MI; ii++)
                ldx4(aFl[ii], aBl + (mbase + ii * 16) * PITCH + aoff);
#pragma unroll
            for (int ii = 0; ii < MI; ii++)
#pragma unroll
                for (int nj = 0; nj < 4; nj++)
                    mma16816(acc[ii][nj], aFl[ii], bFh[nj >> 1][(nj & 1) * 2],
                             bFh[nj >> 1][(nj & 1) * 2 + 1]);
#pragma unroll
            for (int j = 0; j < 2; j++)
                ldx4(bFl[j], bBl + (nbase + j * 16) * PITCH + boff);
#pragma unroll
            for (int ii = 0; ii < MI; ii++)
#pragma unroll
                for (int nj = 0; nj < 4; nj++)
                    mma16816(acc[ii][nj], aFh[ii], bFl[nj >> 1][(nj & 1) * 2],
                             bFl[nj >> 1][(nj & 1) * 2 + 1]);
        }
    }

    const int qr = lane >> 2, qc = lane & 3;
#pragma unroll
    for (int i = 0; i < MI; i++) {
#pragma unroll
        for (int nj = 0; nj < 4; nj++) {
            int n = n0 + nbase + nj * 8 + qc * 2;
#pragma unroll
            for (int h = 0; h < 2; h++) {
                int m = m0 + mbase + i * 16 + qr + h * 8;
                float v0 = acc[i][nj][h * 2], v1 = acc[i][nj][h * 2 + 1];
                if constexpr (EPI == EPI_TANH) {
                    v0 = tanhf(v0 + __ldg(bias + n));
                    v1 = tanhf(v1 + __ldg(bias + n + 1));
                } else if constexpr (EPI == EPI_DA2) {
                    float t0 = tanhf(v0 + __ldg(bias + n));
                    float t1 = tanhf(v1 + __ldg(bias + n + 1));
                    v0 = __ldg(w3 + n) * (1.f - t0 * t0);
                    v1 = __ldg(w3 + n + 1) * (1.f - t1 * t1);
                } else if constexpr (EPI == EPI_MULT) {
                    size_t off = ((size_t)m * NTOT + n) * 2;
                    uint32_t uh = *(const uint32_t*)((const char*)Hh + off);
                    uint32_t ul = *(const uint32_t*)((const char*)Hl + off);
                    float h0 = __bfloat162float(__ushort_as_bfloat16((uint16_t)uh)) +
                               __bfloat162float(__ushort_as_bfloat16((uint16_t)ul));
                    float h1 = __bfloat162float(__ushort_as_bfloat16((uint16_t)(uh >> 16))) +
                               __bfloat162float(__ushort_as_bfloat16((uint16_t)(ul >> 16)));
                    v0 *= (1.f - h0 * h0);
                    v1 *= (1.f - h1 * h1);
                }
                if constexpr (EPI == EPI_SYMP) {
                    float sgn = (n >= 32) ? 1.f : -1.f;
                    *(float2*)(Osym + (size_t)m * 64 + (n ^ 32)) =
                        make_float2(sgn * v0, sgn * v1);
                } else {
                    uint16_t h0, l0, h1, l1;
                    split_bf(v0, h0, l0);
                    split_bf(v1, h1, l1);
                    size_t off = ((size_t)m * NTOT + n) * 2;
                    *(uint32_t*)((char*)Oh + off) = (uint32_t)h0 | ((uint32_t)h1 << 16);
                    *(uint32_t*)((char*)Ol + off) = (uint32_t)l0 | ((uint32_t)l1 << 16);
                }
            }
        }
    }
}

// ---------------- F: small-footprint fp32 SGEMM ------------------------------
__global__ void transpose_k(const float* __restrict__ in, float* __restrict__ out,
                            int R, int C) {
    __shared__ float tile[32][33];
    int c0 = blockIdx.x * 32, r0 = blockIdx.y * 32;
    int tx = threadIdx.x, ty = threadIdx.y;
#pragma unroll
    for (int i = 0; i < 32; i += 8) {
        int r = r0 + ty + i, c = c0 + tx;
        if (r < R && c < C) tile[ty + i][tx] = in[(size_t)r * C + c];
    }
    __syncthreads();
#pragma unroll
    for (int i = 0; i < 32; i += 8) {
        int r = c0 + ty + i, c = r0 + tx;
        if (r < C && c < R) out[(size_t)r * R + c] = tile[tx][ty + i];
    }
}

// 64x64 tile, 128 threads, TM=8 TN=4 -> low regs+smem for co-residency with H.
template <int EPI>
__global__ void __launch_bounds__(128)
fgemm(const float* __restrict__ A, const float* __restrict__ Bm,
      float* __restrict__ C, const float* __restrict__ bias,
      const float* __restrict__ w3, const float* __restrict__ elem,
      int M, int N, int K) {
    constexpr int BM = 64, BN = 64, BK = 16, TM = 8, TN = 4;
    constexpr int NT = 128;
    __shared__ float As[BK][BM];
    __shared__ float Bs[BK][BN];
    const int m0 = blockIdx.y * BM, n0 = blockIdx.x * BN;
    const int tid = threadIdx.x;
    const int tidm = tid / (BN / TN);   // 0..7
    const int tidn = tid % (BN / TN);   // 0..15
    float acc[TM][TN];
#pragma unroll
    for (int i = 0; i < TM; i++)
#pragma unroll
        for (int j = 0; j < TN; j++) acc[i][j] = 0.f;
    for (int k0 = 0; k0 < K; k0 += BK) {
#pragma unroll
        for (int f = tid; f < BM * BK / 4; f += NT) {
            int row = f / (BK / 4);
            int k4 = (f % (BK / 4)) * 4;
            float4 v = *(const float4*)(A + (size_t)(m0 + row) * K + k0 + k4);
            As[k4 + 0][row] = v.x;
            As[k4 + 1][row] = v.y;
            As[k4 + 2][row] = v.z;
            As[k4 + 3][row] = v.w;
        }
#pragma unroll
        for (int f = tid; f < BK * BN / 4; f += NT) {
            int kr = f / (BN / 4);
            int n4 = (f % (BN / 4)) * 4;
            *(float4*)&Bs[kr][n4] = *(const float4*)(Bm + (size_t)(k0 + kr) * N + n0 + n4);
        }
        __syncthreads();
#pragma unroll
        for (int k = 0; k < BK; k++) {
            float a[TM], b[TN];
#pragma unroll
            for (int v = 0; v < TM; v += 4)
                *(float4*)&a[v] = *(const float4*)&As[k][tidm * TM + v];
            *(float4*)&b[0] = *(const float4*)&Bs[k][tidn * TN];
#pragma unroll
            for (int i = 0; i < TM; i++)
#pragma unroll
                for (int j = 0; j < TN; j++) acc[i][j] += a[i] * b[j];
        }
        __syncthreads();
    }
#pragma unroll
    for (int i = 0; i < TM; i++) {
        int m = m0 + tidm * TM + i;
#pragma unroll
        for (int j = 0; j < TN; j++) {
            int n = n0 + tidn * TN + j;
            float v = acc[i][j];
            if constexpr (EPI == EPI_TANH) {
                C[(size_t)m * N + n] = tanhf(v + bias[n]);
            } else if constexpr (EPI == EPI_DA2) {
                float t = tanhf(v + bias[n]);
                C[(size_t)m * N + n] = w3[n] * (1.f - t * t);
            } else if constexpr (EPI == EPI_MULT) {
                float e = elem[(size_t)m * N + n];
                C[(size_t)m * N + n] = v * (1.f - e * e);
            } else {
                int oc = (n + 32) & 63;
                float s = (n >= 32) ? 1.f : -1.f;
                C[(size_t)m * 64 + oc] = s * v;
            }
        }
    }
}

// ---------------- host -------------------------------------------------------
extern "C" void kernel_launch(void* const* d_in, const int* in_sizes, int n_in,
                              void* d_out, int out_size) {
    (void)in_sizes; (void)n_in; (void)out_size;
    const float* x  = (const float*)d_in[1];
    const float* W0 = (const float*)d_in[2];
    const float* b0 = (const float*)d_in[3];
    const float* W1 = (const float*)d_in[4];
    const float* b1 = (const float*)d_in[5];
    const float* W2 = (const float*)d_in[6];
    const float* b2 = (const float*)d_in[7];
    const float* W3 = (const float*)d_in[8];
    float* out = (float*)d_out;

    bf16 *a0h, *a0l, *h0h, *h0l, *h1h, *h1l, *d2h, *d2l, *d1h, *d1l, *d0h, *d0l;
    bf16 *bf0h, *bf0l, *bf1h, *bf1l, *bf2h, *bf2l, *bb2h, *bb2l, *bb1h, *bb1l, *bb0h, *bb0l;
    float *fh0, *fh1, *fda, *fdb, *W1t, *W2t, *W0t;
    cudaGetSymbolAddress((void**)&a0h, g_a0h);  cudaGetSymbolAddress((void**)&a0l, g_a0l);
    cudaGetSymbolAddress((void**)&h0h, g_h0h);  cudaGetSymbolAddress((void**)&h0l, g_h0l);
    cudaGetSymbolAddress((void**)&h1h, g_h1h);  cudaGetSymbolAddress((void**)&h1l, g_h1l);
    cudaGetSymbolAddress((void**)&d2h, g_d2h);  cudaGetSymbolAddress((void**)&d2l, g_d2l);
    cudaGetSymbolAddress((void**)&d1h, g_d1h);  cudaGetSymbolAddress((void**)&d1l, g_d1l);
    cudaGetSymbolAddress((void**)&d0h, g_d0h);  cudaGetSymbolAddress((void**)&d0l, g_d0l);
    cudaGetSymbolAddress((void**)&bf0h, g_bf0h); cudaGetSymbolAddress((void**)&bf0l, g_bf0l);
    cudaGetSymbolAddress((void**)&bf1h, g_bf1h); cudaGetSymbolAddress((void**)&bf1l, g_bf1l);
    cudaGetSymbolAddress((void**)&bf2h, g_bf2h); cudaGetSymbolAddress((void**)&bf2l, g_bf2l);
    cudaGetSymbolAddress((void**)&bb2h, g_bb2h); cudaGetSymbolAddress((void**)&bb2l, g_bb2l);
    cudaGetSymbolAddress((void**)&bb1h, g_bb1h); cudaGetSymbolAddress((void**)&bb1l, g_bb1l);
    cudaGetSymbolAddress((void**)&bb0h, g_bb0h); cudaGetSymbolAddress((void**)&bb0l, g_bb0l);
    cudaGetSymbolAddress((void**)&fh0, g_fh0);  cudaGetSymbolAddress((void**)&fh1, g_fh1);
    cudaGetSymbolAddress((void**)&fda, g_fda);  cudaGetSymbolAddress((void**)&fdb, g_fdb);
    cudaGetSymbolAddress((void**)&W1t, g_W1t);  cudaGetSymbolAddress((void**)&W2t, g_W2t);
    cudaGetSymbolAddress((void**)&W0t, g_W0t);

    cudaStream_t s2;
    cudaStreamCreateWithFlags(&s2, cudaStreamNonBlocking);
    cudaEvent_t e1, e2;
    cudaEventCreateWithFlags(&e1, cudaEventDisableTiming);
    cudaEventCreateWithFlags(&e2, cudaEventDisableTiming);
    cudaEventRecord(e1, 0);
    cudaStreamWaitEvent(s2, e1, 0);

    // ---- F chain on s2 (rows [MH, BATCH)) ----
    const float* xF = x + (size_t)MH * DIN;
    float* outF = out + (size_t)MH * 64;
    dim3 tb(32, 8);
    transpose_k<<<dim3(HID / 32, HID / 32), tb, 0, s2>>>(W1, W1t, HID, HID);
    transpose_k<<<dim3(HID / 32, HID / 32), tb, 0, s2>>>(W2, W2t, HID, HID);
    transpose_k<<<dim3(HID / 32, 2), tb, 0, s2>>>(W0, W0t, DIN, HID);
    dim3 gf(HID / 64, MF / 64);   // (8, 128)
    fgemm<EPI_TANH><<<gf, 128, 0, s2>>>(xF, W0, fh0, b0, nullptr, nullptr, MF, HID, DIN);
    fgemm<EPI_TANH><<<gf, 128, 0, s2>>>(fh0, W1, fh1, b1, nullptr, nullptr, MF, HID, HID);
    fgemm<EPI_DA2><<<gf, 128, 0, s2>>>(fh1, W2, fda, b2, W3, nullptr, MF, HID, HID);
    fgemm<EPI_MULT><<<gf, 128, 0, s2>>>(fda, W2t, fdb, nullptr, nullptr, fh1, MF, HID, HID);
    fgemm<EPI_MULT><<<gf, 128, 0, s2>>>(fdb, W1t, fda, nullptr, nullptr, fh0, MF, HID, HID);
    fgemm<EPI_SYMP><<<dim3(1, MF / 64), 128, 0, s2>>>(
        fda, W0t, outF, nullptr, nullptr, nullptr, MF, DIN, HID);
    cudaEventRecord(e2, s2);

    // ---- H chain on default stream (rows [0, MH)) ----
    convert_x<<<(MH * DIN + 255) / 256, 256>>>(x, a0h, a0l, MH * DIN);
    pack_w<true><<<(HID * DIN + 255) / 256, 256>>>(W0, HID, DIN, bf0h, bf0l);
    pack_w<true><<<(HID * HID + 255) / 256, 256>>>(W1, HID, HID, bf1h, bf1l);
    pack_w<true><<<(HID * HID + 255) / 256, 256>>>(W2, HID, HID, bf2h, bf2l);
    pack_w<false><<<(HID * HID + 255) / 256, 256>>>(W2, HID, HID, bb2h, bb2l);
    pack_w<false><<<(HID * HID + 255) / 256, 256>>>(W1, HID, HID, bb1h, bb1l);
    pack_w<false><<<(DIN * HID + 255) / 256, 256>>>(W0, DIN, HID, bb0h, bb0l);

    constexpr int SM128 = 3 * (4 * 128 * 80);                 // 122880
    constexpr int SM64  = 3 * (2 * 128 * 80 + 2 * 64 * 80);   // 92160
    cudaFuncSetAttribute(hnn_gemm<EPI_TANH, 128>, cudaFuncAttributeMaxDynamicSharedMemorySize, SM128);
    cudaFuncSetAttribute(hnn_gemm<EPI_DA2, 128>,  cudaFuncAttributeMaxDynamicSharedMemorySize, SM128);
    cudaFuncSetAttribute(hnn_gemm<EPI_MULT, 128>, cudaFuncAttributeMaxDynamicSharedMemorySize, SM128);
    cudaFuncSetAttribute(hnn_gemm<EPI_SYMP, 64>,  cudaFuncAttributeMaxDynamicSharedMemorySize, SM64);

    dim3 gh(HID / 128, MH / 128);  // (4, 448)
    hnn_gemm<EPI_TANH, 128><<<gh, 512, SM128>>>(a0h, a0l, bf0h, bf0l, b0, nullptr,
                                                nullptr, nullptr, h0h, h0l, nullptr, DIN, HID);
    hnn_gemm<EPI_TANH, 128><<<gh, 512, SM128>>>(h0h, h0l, bf1h, bf1l, b1, nullptr,
                                                nullptr, nullptr, h1h, h1l, nullptr, HID, HID);
    hnn_gemm<EPI_DA2, 128><<<gh, 512, SM128>>>(h1h, h1l, bf2h, bf2l, b2, W3,
                                               nullptr, nullptr, d2h, d2l, nullptr, HID, HID);
    hnn_gemm<EPI_MULT, 128><<<gh, 512, SM128>>>(d2h, d2l, bb2h, bb2l, nullptr, nullptr,
                                                h1h, h1l, d1h, d1l, nullptr, HID, HID);
    hnn_gemm<EPI_MULT, 128><<<gh, 512, SM128>>>(d1h, d1l, bb1h, bb1l, nullptr, nullptr,
                                                h0h, h0l, d0h, d0l, nullptr, HID, HID);
    hnn_gemm<EPI_SYMP, 64><<<dim3(1, MH / 128), 512, SM64>>>(
        d0h, d0l, bb0h, bb0l, nullptr, nullptr, nullptr, nullptr,
        nullptr, nullptr, out, HID, DIN);

    cudaStreamWaitEvent(0, e2, 0);
    cudaEventDestroy(e1);
    cudaEventDestroy(e2);
    cudaStreamDestroy(s2);
}